// round 9
// baseline (speedup 1.0000x reference)
#include <cuda_runtime.h>
#include <cuda_fp16.h>
#include <math.h>
#include <stdint.h>

#define NB 8192
#define NH 2048
#define NR 64

// fp16 scratch (weights + inter-kernel activations)
__device__ __half g_ww16[NH * NH];
__device__ __half g_uw16[NH * NH];
__device__ __half g_wqkv16[3 * NR * NH];   // rows 0-63 WQ | 64-127 WK | 128-191 WV
__device__ __half g_wo16[NH * NR];
__device__ __half g_hth[NB * NH];          // h_t fp16 (k1 -> k234)

// ---------------------------------------------------------------------------
// helpers (sm_80-compatible; NO 'a'-suffix features)
// ---------------------------------------------------------------------------
__device__ __forceinline__ uint32_t smem_u32(const void* p) {
    uint32_t a;
    asm("{ .reg .u64 t; cvta.to.shared.u64 t, %1; cvt.u32.u64 %0, t; }"
        : "=r"(a) : "l"(p));
    return a;
}
#define LDMATRIX_X4(r, addr)                                                    \
    asm volatile("ldmatrix.sync.aligned.m8n8.x4.shared.b16 {%0,%1,%2,%3}, [%4];"\
        : "=r"((r)[0]), "=r"((r)[1]), "=r"((r)[2]), "=r"((r)[3]) : "r"(addr))

__device__ __forceinline__ void mma_f16(float c[4], const uint32_t a[4],
                                        uint32_t b0, uint32_t b1) {
    asm volatile(
        "mma.sync.aligned.m16n8k16.row.col.f32.f16.f16.f32 "
        "{%0,%1,%2,%3}, {%4,%5,%6,%7}, {%8,%9}, {%0,%1,%2,%3};"
        : "+f"(c[0]), "+f"(c[1]), "+f"(c[2]), "+f"(c[3])
        : "r"(a[0]), "r"(a[1]), "r"(a[2]), "r"(a[3]), "r"(b0), "r"(b1));
}

#define CP_ASYNC16(saddr, gptr)                                                \
    asm volatile("cp.async.cg.shared.global [%0], [%1], 16;"                   \
        :: "r"(saddr), "l"(gptr) : "memory")
#define CP_COMMIT() asm volatile("cp.async.commit_group;" ::: "memory")
#define CP_WAIT1()  asm volatile("cp.async.wait_group 1;" ::: "memory")
#define CP_WAIT0()  asm volatile("cp.async.wait_group 0;" ::: "memory")

__device__ __forceinline__ void sts_u16(uint32_t addr, uint16_t v) {
    asm volatile("st.shared.u16 [%0], %1;" :: "r"(addr), "h"(v));
}

// fp32 float4 -> two half2 -> 8B swizzled shared store (A-operand layout)
__device__ __forceinline__ void sts_pair(uint32_t base, int c, float4 v) {
    const int row = c >> 4, f4 = c & 15;
    __half2 h0 = __floats2half2_rn(v.x, v.y);
    __half2 h1 = __floats2half2_rn(v.z, v.w);
    const uint32_t u0 = *reinterpret_cast<uint32_t*>(&h0);
    const uint32_t u1 = *reinterpret_cast<uint32_t*>(&h1);
    const uint32_t addr = base + row * 128 +
                          ((((f4 >> 1) ^ (row & 7))) << 4) + (f4 & 1) * 8;
    asm volatile("st.shared.v2.b32 [%0], {%1,%2};" :: "r"(addr), "r"(u0), "r"(u1));
}

// ---------------------------------------------------------------------------
// pre-pass: WEIGHTS ONLY fp32 -> fp16 (activations converted in-kernel now)
// segments (float4 units): ww 1048576 | uw 1048576 | wq/wk/wv 32768 ea | wo 32768
// ---------------------------------------------------------------------------
#define CVTW_TOTAL4 2228224
__global__ __launch_bounds__(256)
void cvt_w(const float* __restrict__ ww, const float* __restrict__ uw,
           const float* __restrict__ wq, const float* __restrict__ wk,
           const float* __restrict__ wv, const float* __restrict__ wo)
{
    const int base = blockIdx.x * 1024 + threadIdx.x;
#pragma unroll
    for (int it = 0; it < 4; ++it) {
        const int i = base + it * 256;
        if (i >= CVTW_TOTAL4) return;
        const float* src; __half* dst; int off;
        if (i < 1048576)      { src = ww; dst = g_ww16;              off = i; }
        else if (i < 2097152) { src = uw; dst = g_uw16;              off = i - 1048576; }
        else if (i < 2129920) { src = wq; dst = g_wqkv16;            off = i - 2097152; }
        else if (i < 2162688) { src = wk; dst = g_wqkv16 + 64 * NH;  off = i - 2129920; }
        else if (i < 2195456) { src = wv; dst = g_wqkv16 + 128 * NH; off = i - 2162688; }
        else                  { src = wo; dst = g_wo16;              off = i - 2195456; }
        float4 v = ((const float4*)src)[off];
        ((__half2*)dst)[2 * off]     = __floats2half2_rn(v.x, v.y);
        ((__half2*)dst)[2 * off + 1] = __floats2half2_rn(v.z, v.w);
    }
}

// ---------------------------------------------------------------------------
// Kernel 1 (fp16 mma, in-kernel A conversion):
//   h_t = (1-sigmoid(alpha))*h_prev + tanh(h_prev@W_w^T + x_t@U_w^T + U_b)
// BM=128, BN=128, BK=64, 256 thr (2x4 warps, warp tile 64x32).
// A: fp32 LDG -> reg cvt -> STS fp16 (2-stage, interleaved with MMA).
// B: fp16 weights via cp.async (2-stage, one group in flight).
// SMEM: A0[0,16K) A1[16K,32K) B0[32K,48K) B1[48K,64K) = 64KB -> occ 2.
// ---------------------------------------------------------------------------
#define K1_SMEM 65536

__global__ __launch_bounds__(256, 2)
void k1_liquid_f16(const float* __restrict__ h_prev,
                   const float* __restrict__ x_t,
                   const float* __restrict__ U_b,
                   const float* __restrict__ alpha_raw,
                   float* __restrict__ h_t)
{
    extern __shared__ char sm[];
    const uint32_t sbase = smem_u32(sm);

    const int tid  = threadIdx.x;
    const int wid  = tid >> 5;
    const int lane = tid & 31;
    const int warp_m = wid & 1;
    const int warp_n = wid >> 1;
    const int m0 = blockIdx.y * 128;
    const int n0 = blockIdx.x * 128;

    float acc[4][4][4];
#pragma unroll
    for (int a = 0; a < 4; ++a)
#pragma unroll
        for (int b = 0; b < 4; ++b)
#pragma unroll
            for (int d = 0; d < 4; ++d) acc[a][b][d] = 0.f;

    const int rl16 = lane & 15;
    const int ksel = lane >> 4;
    uint32_t aOff[4]; int aSwz[4];
    uint32_t bOff[2]; int bSwz[2];
#pragma unroll
    for (int mt = 0; mt < 4; ++mt) {
        const int r = warp_m * 64 + mt * 16 + rl16;
        aOff[mt] = r * 128; aSwz[mt] = r & 7;
    }
#pragma unroll
    for (int p = 0; p < 2; ++p) {
        const int r = warp_n * 32 + p * 16 + rl16;
        bOff[p] = 32768 + r * 128; bSwz[p] = r & 7;
    }

    // ---------------- prologue: tile 0 into buffer 0 ----------------
    {
        // B(0) via cp.async
#pragma unroll
        for (int i = 0; i < 4; ++i) {
            const int id = tid + 256 * i;
            const int row = id >> 3, c = id & 7;
            CP_ASYNC16(sbase + 32768 + row * 128 + ((c ^ (row & 7)) << 4),
                       g_ww16 + (size_t)(n0 + row) * NH + c * 8);
        }
        CP_COMMIT();
        // A(0): fp32 LDG + cvt + STS
#pragma unroll
        for (int h = 0; h < 2; ++h) {
            float4 v0, v1, v2, v3;
            const int c0 = tid + 256 * (h * 4 + 0);
            const int c1 = tid + 256 * (h * 4 + 1);
            const int c2 = tid + 256 * (h * 4 + 2);
            const int c3 = tid + 256 * (h * 4 + 3);
            v0 = *(const float4*)(h_prev + (size_t)(m0 + (c0 >> 4)) * NH + (c0 & 15) * 4);
            v1 = *(const float4*)(h_prev + (size_t)(m0 + (c1 >> 4)) * NH + (c1 & 15) * 4);
            v2 = *(const float4*)(h_prev + (size_t)(m0 + (c2 >> 4)) * NH + (c2 & 15) * 4);
            v3 = *(const float4*)(h_prev + (size_t)(m0 + (c3 >> 4)) * NH + (c3 & 15) * 4);
            sts_pair(sbase, c0, v0); sts_pair(sbase, c1, v1);
            sts_pair(sbase, c2, v2); sts_pair(sbase, c3, v3);
        }
        CP_WAIT0();
        __syncthreads();
    }

    // ---------------- main loop: 64 k-tiles, 2-stage ----------------
    for (int kt = 0; kt < 64; ++kt) {
        const int b = kt & 1;
        const uint32_t stA = sbase + b * 16384;
        const uint32_t stB = sbase + 32768 + b * 16384;
        const uint32_t nxA = sbase + (b ^ 1) * 16384;
        const bool more = (kt + 1 < 64);

        // issue B(kt+1) cp.async (readers of that buffer finished last kt)
        if (more) {
            const __half* Bsrc = (kt + 1 < 32) ? g_ww16 : g_uw16;
            const int k0 = ((kt + 1) & 31) << 6;
            const uint32_t sb = sbase + 32768 + (b ^ 1) * 16384;
#pragma unroll
            for (int i = 0; i < 4; ++i) {
                const int id = tid + 256 * i;
                const int row = id >> 3, c = id & 7;
                CP_ASYNC16(sb + row * 128 + ((c ^ (row & 7)) << 4),
                           Bsrc + (size_t)(n0 + row) * NH + k0 + c * 8);
            }
            CP_COMMIT();
        }

        const float* An = (kt + 1 < 32) ? h_prev : x_t;
        const int k0n = ((kt + 1) & 31) << 6;
        float4 v0, v1, v2, v3;
        int c0 = 0, c1 = 0, c2 = 0, c3 = 0;

        if (more) {   // LDG batch 0
            c0 = tid;        c1 = tid + 256;
            c2 = tid + 512;  c3 = tid + 768;
            v0 = *(const float4*)(An + (size_t)(m0 + (c0 >> 4)) * NH + k0n + (c0 & 15) * 4);
            v1 = *(const float4*)(An + (size_t)(m0 + (c1 >> 4)) * NH + k0n + (c1 & 15) * 4);
            v2 = *(const float4*)(An + (size_t)(m0 + (c2 >> 4)) * NH + k0n + (c2 & 15) * 4);
            v3 = *(const float4*)(An + (size_t)(m0 + (c3 >> 4)) * NH + k0n + (c3 & 15) * 4);
        }

#pragma unroll
        for (int ks = 0; ks < 4; ++ks) {
            const int chunk = ks * 2 + ksel;
            uint32_t a[4][4], bb[2][4];
#pragma unroll
            for (int mt = 0; mt < 4; ++mt)
                LDMATRIX_X4(a[mt], stA + aOff[mt] - 0 + ((chunk ^ aSwz[mt]) << 4));
#pragma unroll
            for (int p = 0; p < 2; ++p)
                LDMATRIX_X4(bb[p], stB + (bOff[p] - 32768) + ((chunk ^ bSwz[p]) << 4));
#pragma unroll
            for (int mt = 0; mt < 4; ++mt)
#pragma unroll
                for (int nt = 0; nt < 4; ++nt)
                    mma_f16(acc[mt][nt], a[mt],
                            bb[nt >> 1][nt & 1], bb[nt >> 1][2 + (nt & 1)]);

            if (ks == 0 && more) {
                // STS batch 0, then LDG batch 1
                sts_pair(nxA, c0, v0); sts_pair(nxA, c1, v1);
                sts_pair(nxA, c2, v2); sts_pair(nxA, c3, v3);
                c0 = tid + 1024; c1 = tid + 1280;
                c2 = tid + 1536; c3 = tid + 1792;
                v0 = *(const float4*)(An + (size_t)(m0 + (c0 >> 4)) * NH + k0n + (c0 & 15) * 4);
                v1 = *(const float4*)(An + (size_t)(m0 + (c1 >> 4)) * NH + k0n + (c1 & 15) * 4);
                v2 = *(const float4*)(An + (size_t)(m0 + (c2 >> 4)) * NH + k0n + (c2 & 15) * 4);
                v3 = *(const float4*)(An + (size_t)(m0 + (c3 >> 4)) * NH + k0n + (c3 & 15) * 4);
            }
            if (ks == 2 && more) {
                sts_pair(nxA, c0, v0); sts_pair(nxA, c1, v1);
                sts_pair(nxA, c2, v2); sts_pair(nxA, c3, v3);
            }
        }

        if (more) CP_WAIT0();
        __syncthreads();
    }

    // ---------------- epilogue (unchanged) ----------------
    const int g = lane >> 2, tig = lane & 3;
    const int mBase = m0 + warp_m * 64;
    const int nBase = n0 + warp_n * 32;
#pragma unroll
    for (int nt = 0; nt < 4; ++nt) {
        const int n = nBase + nt * 8 + tig * 2;
        const float om0 = 1.f / (1.f + __expf(alpha_raw[n]));
        const float om1 = 1.f / (1.f + __expf(alpha_raw[n + 1]));
        const float bi0 = U_b[n], bi1 = U_b[n + 1];
#pragma unroll
        for (int mt = 0; mt < 4; ++mt) {
            int m = mBase + mt * 16 + g;
            float2 hp = *(const float2*)(h_prev + (size_t)m * NH + n);
            float2 o;
            o.x = om0 * hp.x + tanhf(acc[mt][nt][0] + bi0);
            o.y = om1 * hp.y + tanhf(acc[mt][nt][1] + bi1);
            *(float2*)(h_t + (size_t)m * NH + n) = o;
            *(__half2*)(g_hth + (size_t)m * NH + n) = __floats2half2_rn(o.x, o.y);
            m += 8;
            hp = *(const float2*)(h_prev + (size_t)m * NH + n);
            o.x = om0 * hp.x + tanhf(acc[mt][nt][2] + bi0);
            o.y = om1 * hp.y + tanhf(acc[mt][nt][3] + bi1);
            *(float2*)(h_t + (size_t)m * NH + n) = o;
            *(__half2*)(g_hth + (size_t)m * NH + n) = __floats2half2_rn(o.x, o.y);
        }
    }
}

// ---------------------------------------------------------------------------
// Kernel 234 (fused, unchanged from R8): per 64-row batch panel,
//   A) qkv = h_t @ [WQ;WK;WV]^T   B) routed softmax   C) y = gamma*rv@WO^T + x_t
// ---------------------------------------------------------------------------
#define K234_STAGE 32768
#define K234_SMEM  98304
#define QSTR 193
#define RV_OFF 53248
#define WO_OFF 61440

__global__ __launch_bounds__(256, 1)
void k234_fused(const float* __restrict__ x_t,
                const float* __restrict__ gamma,
                float* __restrict__ y)
{
    extern __shared__ char sm[];
    const uint32_t sbase = smem_u32(sm);
    float* smf = (float*)sm;

    const int tid  = threadIdx.x;
    const int wid  = tid >> 5;
    const int lane = tid & 31;
    const int m0   = blockIdx.x * 64;
    const unsigned full = 0xffffffffu;

    const int rl16 = lane & 15;
    const int ksel = lane >> 4;
    const int g    = lane >> 2;
    const int tig  = lane & 3;

    // ================= Phase A: QKV GEMM (BM=64, BN=192) =================
    {
        const int warp_m = wid & 1;
        const int warp_n = wid >> 1;

        auto load_stage = [&](int kt, int s) {
            const int k0 = kt << 6;
            const uint32_t sa = sbase + s * K234_STAGE;
            const uint32_t sb = sa + 8192;
#pragma unroll
            for (int i = 0; i < 2; ++i) {
                const int id = tid + 256 * i;
                const int row = id >> 3, c = id & 7;
                CP_ASYNC16(sa + row * 128 + ((c ^ (row & 7)) << 4),
                           g_hth + (size_t)(m0 + row) * NH + k0 + c * 8);
            }
#pragma unroll
            for (int i = 0; i < 6; ++i) {
                const int id = tid + 256 * i;
                const int row = id >> 3, c = id & 7;
                CP_ASYNC16(sb + row * 128 + ((c ^ (row & 7)) << 4),
                           g_wqkv16 + (size_t)row * NH + k0 + c * 8);
            }
        };

        float acc[2][6][4];
#pragma unroll
        for (int a = 0; a < 2; ++a)
#pragma unroll
            for (int b = 0; b < 6; ++b)
#pragma unroll
                for (int d = 0; d < 4; ++d) acc[a][b][d] = 0.f;

        load_stage(0, 0); CP_COMMIT();
        load_stage(1, 1); CP_COMMIT();

        uint32_t aOff[2]; int aSwz[2];
        uint32_t bOff[3]; int bSwz[3];
#pragma unroll
        for (int mt = 0; mt < 2; ++mt) {
            const int r = warp_m * 32 + mt * 16 + rl16;
            aOff[mt] = r * 128; aSwz[mt] = r & 7;
        }
#pragma unroll
        for (int p = 0; p < 3; ++p) {
            const int r = warp_n * 48 + p * 16 + rl16;
            bOff[p] = 8192 + r * 128; bSwz[p] = r & 7;
        }

        for (int kt = 0; kt < 32; ++kt) {
            const int s = kt % 3;
            CP_WAIT1();
            __syncthreads();
            if (kt + 2 < 32) load_stage(kt + 2, (kt + 2) % 3);
            CP_COMMIT();

            const uint32_t stage = sbase + s * K234_STAGE;
#pragma unroll
            for (int ks = 0; ks < 4; ++ks) {
                const int chunk = ks * 2 + ksel;
                uint32_t a[2][4], b[3][4];
#pragma unroll
                for (int mt = 0; mt < 2; ++mt)
                    LDMATRIX_X4(a[mt], stage + aOff[mt] + ((chunk ^ aSwz[mt]) << 4));
#pragma unroll
                for (int p = 0; p < 3; ++p)
                    LDMATRIX_X4(b[p], stage + bOff[p] + ((chunk ^ bSwz[p]) << 4));
#pragma unroll
                for (int mt = 0; mt < 2; ++mt)
#pragma unroll
                    for (int nt = 0; nt < 6; ++nt)
                        mma_f16(acc[mt][nt], a[mt],
                                b[nt >> 1][nt & 1], b[nt >> 1][2 + (nt & 1)]);
            }
        }

        CP_WAIT0();
        __syncthreads();

#pragma unroll
        for (int nt = 0; nt < 6; ++nt) {
            const int n = warp_n * 48 + nt * 8 + tig * 2;
#pragma unroll
            for (int mt = 0; mt < 2; ++mt) {
                int m = warp_m * 32 + mt * 16 + g;
                smf[m * QSTR + n]     = acc[mt][nt][0];
                smf[m * QSTR + n + 1] = acc[mt][nt][1];
                m += 8;
                smf[m * QSTR + n]     = acc[mt][nt][2];
                smf[m * QSTR + n + 1] = acc[mt][nt][3];
            }
        }
    }
    __syncthreads();

    // ================= Phase B: softmax routing =================
    {
#pragma unroll 1
        for (int rr = 0; rr < 8; ++rr) {
            const int r = wid * 8 + rr;
            const float* qk = smf + r * QSTR;
            const float q0s = 0.125f * qk[lane];
            const float q1s = 0.125f * qk[lane + 32];
            const float k0 = qk[64 + lane],  k1 = qk[96 + lane];
            const float v0 = qk[128 + lane], v1 = qk[160 + lane];

            float se0 = 0.f, sd0 = 0.f, se1 = 0.f, sd1 = 0.f;
#pragma unroll 8
            for (int j = 0; j < 32; ++j) {
                const float kj = __shfl_sync(full, k0, j);
                const float vj = __shfl_sync(full, v0, j);
                const float e0 = __expf(q0s * kj);
                const float e1 = __expf(q1s * kj);
                se0 += e0; sd0 = fmaf(e0, vj, sd0);
                se1 += e1; sd1 = fmaf(e1, vj, sd1);
            }
#pragma unroll 8
            for (int j = 0; j < 32; ++j) {
                const float kj = __shfl_sync(full, k1, j);
                const float vj = __shfl_sync(full, v1, j);
                const float e0 = __expf(q0s * kj);
                const float e1 = __expf(q1s * kj);
                se0 += e0; sd0 = fmaf(e0, vj, sd0);
                se1 += e1; sd1 = fmaf(e1, vj, sd1);
            }

            const int c0 = lane, c1 = lane + 32;
            sts_u16(sbase + RV_OFF + r * 128 +
                        (((c0 >> 3) ^ (r & 7)) << 4) + (c0 & 7) * 2,
                    __half_as_ushort(__float2half(sd0 / se0)));
            sts_u16(sbase + RV_OFF + r * 128 +
                        (((c1 >> 3) ^ (r & 7)) << 4) + (c1 & 7) * 2,
                    __half_as_ushort(__float2half(sd1 / se1)));
        }
    }
    __syncthreads();

    // ================= Phase C: y = gamma*(rv @ WO^T) + x_t =================
    {
        const int warp_m = wid & 1;
        const int warp_n = wid >> 1;
        const float gm = gamma[0];

        uint32_t fa[2][4][4];
#pragma unroll
        for (int mt = 0; mt < 2; ++mt) {
            const int r = warp_m * 32 + mt * 16 + rl16;
#pragma unroll
            for (int ks = 0; ks < 4; ++ks) {
                const int chunk = ks * 2 + ksel;
                LDMATRIX_X4(fa[mt][ks],
                            sbase + RV_OFF + r * 128 + ((chunk ^ (r & 7)) << 4));
            }
        }

        auto load_wo = [&](int t, int buf) {
            const uint32_t sb = sbase + WO_OFF + buf * 16384;
#pragma unroll
            for (int i = 0; i < 4; ++i) {
                const int id = tid + 256 * i;
                const int row = id >> 3, c = id & 7;
                CP_ASYNC16(sb + row * 128 + ((c ^ (row & 7)) << 4),
                           g_wo16 + (size_t)(t * 128 + row) * NR + c * 8);
            }
        };

        load_wo(0, 0); CP_COMMIT();

        for (int t = 0; t < 16; ++t) {
            if (t + 1 < 16) { load_wo(t + 1, (t + 1) & 1); CP_COMMIT(); CP_WAIT1(); }
            else            { CP_WAIT0(); }
            __syncthreads();

            const uint32_t sb = sbase + WO_OFF + (t & 1) * 16384;
            float acc[2][4][4];
#pragma unroll
            for (int a = 0; a < 2; ++a)
#pragma unroll
                for (int b = 0; b < 4; ++b)
#pragma unroll
                    for (int d = 0; d < 4; ++d) acc[a][b][d] = 0.f;

#pragma unroll
            for (int ks = 0; ks < 4; ++ks) {
                const int chunk = ks * 2 + ksel;
                uint32_t b[2][4];
#pragma unroll
                for (int p = 0; p < 2; ++p) {
                    const int r = warp_n * 32 + p * 16 + rl16;
                    LDMATRIX_X4(b[p], sb + r * 128 + ((chunk ^ (r & 7)) << 4));
                }
#pragma unroll
                for (int mt = 0; mt < 2; ++mt)
#pragma unroll
                    for (int nt = 0; nt < 4; ++nt)
                        mma_f16(acc[mt][nt], fa[mt][ks],
                                b[nt >> 1][nt & 1], b[nt >> 1][2 + (nt & 1)]);
            }

            const int nBase = t * 128 + warp_n * 32;
#pragma unroll
            for (int nt = 0; nt < 4; ++nt) {
                const int n = nBase + nt * 8 + tig * 2;
#pragma unroll
                for (int mt = 0; mt < 2; ++mt) {
                    int m = m0 + warp_m * 32 + mt * 16 + g;
                    float2 xv = *(const float2*)(x_t + (size_t)m * NH + n);
                    float2 o;
                    o.x = fmaf(gm, acc[mt][nt][0], xv.x);
                    o.y = fmaf(gm, acc[mt][nt][1], xv.y);
                    *(float2*)(y + (size_t)m * NH + n) = o;
                    m += 8;
                    xv = *(const float2*)(x_t + (size_t)m * NH + n);
                    o.x = fmaf(gm, acc[mt][nt][2], xv.x);
                    o.y = fmaf(gm, acc[mt][nt][3], xv.y);
                    *(float2*)(y + (size_t)m * NH + n) = o;
                }
            }
            __syncthreads();
        }
    }
}

// ---------------------------------------------------------------------------
extern "C" void kernel_launch(void* const* d_in, const int* in_sizes, int n_in,
                              void* d_out, int out_size)
{
    const float* h_prev    = (const float*)d_in[0];
    const float* x_t       = (const float*)d_in[1];
    const float* U_w       = (const float*)d_in[2];
    const float* U_b       = (const float*)d_in[3];
    const float* W_w       = (const float*)d_in[4];
    const float* alpha_raw = (const float*)d_in[5];
    const float* WQ        = (const float*)d_in[6];
    const float* WK        = (const float*)d_in[7];
    const float* WV        = (const float*)d_in[8];
    const float* WO        = (const float*)d_in[9];
    const float* gamma     = (const float*)d_in[10];

    float* h_t = (float*)d_out;
    float* y_t = h_t + (size_t)NB * NH;

    cudaFuncSetAttribute(k1_liquid_f16,
                         cudaFuncAttributeMaxDynamicSharedMemorySize, K1_SMEM);
    cudaFuncSetAttribute(k234_fused,
                         cudaFuncAttributeMaxDynamicSharedMemorySize, K234_SMEM);

    cvt_w<<<(CVTW_TOTAL4 + 1023) / 1024, 256>>>(W_w, U_w, WQ, WK, WV, WO);

    dim3 g1(NH / 128, NB / 128);                      // 1024 CTAs
    k1_liquid_f16<<<g1, 256, K1_SMEM>>>(h_prev, x_t, U_b, alpha_raw, h_t);

    k234_fused<<<NB / 64, 256, K234_SMEM>>>(x_t, gamma, y_t);
}

// round 10
// speedup vs baseline: 1.1207x; 1.1207x over previous
#include <cuda_runtime.h>
#include <cuda_fp16.h>
#include <math.h>
#include <stdint.h>

#define NB 8192
#define NH 2048
#define NR 64

// fp16 scratch
__device__ __half g_hp16[NB * NH];
__device__ __half g_xt16[NB * NH];
__device__ __half g_ww16[NH * NH];
__device__ __half g_uw16[NH * NH];
__device__ __half g_wqkv16[3 * NR * NH];   // rows 0-63 WQ | 64-127 WK | 128-191 WV
__device__ __half g_wo16[NH * NR];
__device__ __half g_hth[NB * NH];          // h_t fp16 (k1 -> k234)

// ---------------------------------------------------------------------------
// helpers (sm_80-compatible; NO 'a'-suffix features)
// ---------------------------------------------------------------------------
__device__ __forceinline__ uint32_t smem_u32(const void* p) {
    uint32_t a;
    asm("{ .reg .u64 t; cvta.to.shared.u64 t, %1; cvt.u32.u64 %0, t; }"
        : "=r"(a) : "l"(p));
    return a;
}
#define LDMATRIX_X4(r, addr)                                                    \
    asm volatile("ldmatrix.sync.aligned.m8n8.x4.shared.b16 {%0,%1,%2,%3}, [%4];"\
        : "=r"((r)[0]), "=r"((r)[1]), "=r"((r)[2]), "=r"((r)[3]) : "r"(addr))

__device__ __forceinline__ void mma_f16(float c[4], const uint32_t a[4],
                                        uint32_t b0, uint32_t b1) {
    asm volatile(
        "mma.sync.aligned.m16n8k16.row.col.f32.f16.f16.f32 "
        "{%0,%1,%2,%3}, {%4,%5,%6,%7}, {%8,%9}, {%0,%1,%2,%3};"
        : "+f"(c[0]), "+f"(c[1]), "+f"(c[2]), "+f"(c[3])
        : "r"(a[0]), "r"(a[1]), "r"(a[2]), "r"(a[3]), "r"(b0), "r"(b1));
}

#define CP_ASYNC16(saddr, gptr)                                                \
    asm volatile("cp.async.cg.shared.global [%0], [%1], 16;"                   \
        :: "r"(saddr), "l"(gptr) : "memory")
#define CP_COMMIT() asm volatile("cp.async.commit_group;" ::: "memory")
#define CP_WAIT1()  asm volatile("cp.async.wait_group 1;" ::: "memory")
#define CP_WAIT0()  asm volatile("cp.async.wait_group 0;" ::: "memory")

__device__ __forceinline__ void sts_u16(uint32_t addr, uint16_t v) {
    asm volatile("st.shared.u16 [%0], %1;" :: "r"(addr), "h"(v));
}

// ---------------------------------------------------------------------------
// fused pre-pass: all fp32 -> fp16 in one kernel (R8 version — known good)
// ---------------------------------------------------------------------------
#define CVT_TOTAL4 10616832
__global__ __launch_bounds__(256)
void cvt_all(const float* __restrict__ hp, const float* __restrict__ xt,
             const float* __restrict__ ww, const float* __restrict__ uw,
             const float* __restrict__ wq, const float* __restrict__ wk,
             const float* __restrict__ wv, const float* __restrict__ wo)
{
    const int base = blockIdx.x * 1024 + threadIdx.x;
#pragma unroll
    for (int it = 0; it < 4; ++it) {
        const int i = base + it * 256;
        if (i >= CVT_TOTAL4) return;
        const float* src; __half* dst; int off;
        if (i < 4194304)        { src = hp; dst = g_hp16; off = i; }
        else if (i < 8388608)   { src = xt; dst = g_xt16; off = i - 4194304; }
        else if (i < 9437184)   { src = ww; dst = g_ww16; off = i - 8388608; }
        else if (i < 10485760)  { src = uw; dst = g_uw16; off = i - 9437184; }
        else if (i < 10518528)  { src = wq; dst = g_wqkv16;              off = i - 10485760; }
        else if (i < 10551296)  { src = wk; dst = g_wqkv16 + 64 * NH;    off = i - 10518528; }
        else if (i < 10584064)  { src = wv; dst = g_wqkv16 + 128 * NH;   off = i - 10551296; }
        else                    { src = wo; dst = g_wo16;                off = i - 10584064; }
        float4 v = ((const float4*)src)[off];
        ((__half2*)dst)[2 * off]     = __floats2half2_rn(v.x, v.y);
        ((__half2*)dst)[2 * off + 1] = __floats2half2_rn(v.z, v.w);
    }
}

// ---------------------------------------------------------------------------
// Kernel 1 (fp16 mma): h_t = (1-sigmoid(alpha))*h_prev
//                            + tanh(h_prev@W_w^T + x_t@U_w^T + U_b)
// RE-TILED: BM=128, BN=64, BK=64, 256 thr (4x2 warps, warp tile 32x32).
// 3-stage cp.async (24KB/stage); smem request padded to 96KB to pin occ=2.
// 2048 CTAs over 296 slots = 6.92 -> makespan 7, ~1% tail (vs 13% at 1024).
// ---------------------------------------------------------------------------
#define K1_STAGE 24576                          // A 16KB + B 8KB
#define K1_SMEM  98304                          // 3 stages used; padded -> occ 2

__global__ __launch_bounds__(256, 2)
void k1_liquid_f16(const float* __restrict__ h_prev,
                   const float* __restrict__ U_b,
                   const float* __restrict__ alpha_raw,
                   float* __restrict__ h_t)
{
    extern __shared__ char sm[];
    const uint32_t sbase = smem_u32(sm);

    const int tid  = threadIdx.x;
    const int wid  = tid >> 5;
    const int lane = tid & 31;
    const int warp_m = wid & 3;       // 4 warps over M=128 (32 rows each)
    const int warp_n = wid >> 2;      // 2 warps over N=64  (32 cols each)
    const int m0 = blockIdx.y * 128;  // batch tile
    const int n0 = blockIdx.x * 64;   // hidden tile

    auto load_stage = [&](int kt, int s) {
        const __half* Asrc = (kt < 32) ? g_hp16 : g_xt16;
        const __half* Bsrc = (kt < 32) ? g_ww16 : g_uw16;
        const int k0 = (kt & 31) << 6;
        const uint32_t sa = sbase + s * K1_STAGE;
        const uint32_t sb = sa + 16384;
#pragma unroll
        for (int i = 0; i < 4; ++i) {            // A: 1024 x 16B / 256 thr
            const int id = tid + 256 * i;
            const int row = id >> 3, c = id & 7;
            CP_ASYNC16(sa + row * 128 + ((c ^ (row & 7)) << 4),
                       Asrc + (size_t)(m0 + row) * NH + k0 + c * 8);
        }
#pragma unroll
        for (int i = 0; i < 2; ++i) {            // B: 512 x 16B / 256 thr
            const int id = tid + 256 * i;
            const int row = id >> 3, c = id & 7;
            CP_ASYNC16(sb + row * 128 + ((c ^ (row & 7)) << 4),
                       Bsrc + (size_t)(n0 + row) * NH + k0 + c * 8);
        }
    };

    float acc[2][4][4];
#pragma unroll
    for (int a = 0; a < 2; ++a)
#pragma unroll
        for (int b = 0; b < 4; ++b)
#pragma unroll
            for (int d = 0; d < 4; ++d) acc[a][b][d] = 0.f;

    load_stage(0, 0); CP_COMMIT();
    load_stage(1, 1); CP_COMMIT();

    const int rl16 = lane & 15;
    const int ksel = lane >> 4;
    uint32_t aOff[2]; int aSwz[2];
    uint32_t bOff[2]; int bSwz[2];
#pragma unroll
    for (int mt = 0; mt < 2; ++mt) {
        const int r = warp_m * 32 + mt * 16 + rl16;
        aOff[mt] = r * 128; aSwz[mt] = r & 7;
    }
#pragma unroll
    for (int p = 0; p < 2; ++p) {
        const int r = warp_n * 32 + p * 16 + rl16;
        bOff[p] = 16384 + r * 128; bSwz[p] = r & 7;
    }

    for (int kt = 0; kt < 64; ++kt) {
        const int s = kt % 3;
        CP_WAIT1();
        __syncthreads();
        if (kt + 2 < 64) load_stage(kt + 2, (kt + 2) % 3);
        CP_COMMIT();

        const uint32_t stage = sbase + s * K1_STAGE;
#pragma unroll
        for (int ks = 0; ks < 4; ++ks) {
            const int chunk = ks * 2 + ksel;
            uint32_t a[2][4], b[2][4];
#pragma unroll
            for (int mt = 0; mt < 2; ++mt)
                LDMATRIX_X4(a[mt], stage + aOff[mt] + ((chunk ^ aSwz[mt]) << 4));
#pragma unroll
            for (int p = 0; p < 2; ++p)
                LDMATRIX_X4(b[p], stage + bOff[p] + ((chunk ^ bSwz[p]) << 4));
#pragma unroll
            for (int mt = 0; mt < 2; ++mt)
#pragma unroll
                for (int nt = 0; nt < 4; ++nt)
                    mma_f16(acc[mt][nt], a[mt],
                            b[nt >> 1][nt & 1], b[nt >> 1][2 + (nt & 1)]);
        }
    }

    // epilogue: fp32 gating + tanh; also emit fp16 h_t copy for k234
    const int g = lane >> 2, tig = lane & 3;
    const int mBase = m0 + warp_m * 32;
    const int nBase = n0 + warp_n * 32;
#pragma unroll
    for (int nt = 0; nt < 4; ++nt) {
        const int n = nBase + nt * 8 + tig * 2;
        const float om0 = 1.f / (1.f + __expf(alpha_raw[n]));
        const float om1 = 1.f / (1.f + __expf(alpha_raw[n + 1]));
        const float bi0 = U_b[n], bi1 = U_b[n + 1];
#pragma unroll
        for (int mt = 0; mt < 2; ++mt) {
            int m = mBase + mt * 16 + g;
            float2 hp = *(const float2*)(h_prev + (size_t)m * NH + n);
            float2 o;
            o.x = om0 * hp.x + tanhf(acc[mt][nt][0] + bi0);
            o.y = om1 * hp.y + tanhf(acc[mt][nt][1] + bi1);
            *(float2*)(h_t + (size_t)m * NH + n) = o;
            *(__half2*)(g_hth + (size_t)m * NH + n) = __floats2half2_rn(o.x, o.y);
            m += 8;
            hp = *(const float2*)(h_prev + (size_t)m * NH + n);
            o.x = om0 * hp.x + tanhf(acc[mt][nt][2] + bi0);
            o.y = om1 * hp.y + tanhf(acc[mt][nt][3] + bi1);
            *(float2*)(h_t + (size_t)m * NH + n) = o;
            *(__half2*)(g_hth + (size_t)m * NH + n) = __floats2half2_rn(o.x, o.y);
        }
    }
}

// ---------------------------------------------------------------------------
// Kernel 234 (fused, unchanged from R8): per 64-row batch panel,
//   A) qkv = h_t @ [WQ;WK;WV]^T   B) routed softmax   C) y = gamma*rv@WO^T + x_t
// ---------------------------------------------------------------------------
#define K234_STAGE 32768
#define K234_SMEM  98304
#define QSTR 193
#define RV_OFF 53248
#define WO_OFF 61440

__global__ __launch_bounds__(256, 1)
void k234_fused(const float* __restrict__ x_t,
                const float* __restrict__ gamma,
                float* __restrict__ y)
{
    extern __shared__ char sm[];
    const uint32_t sbase = smem_u32(sm);
    float* smf = (float*)sm;

    const int tid  = threadIdx.x;
    const int wid  = tid >> 5;
    const int lane = tid & 31;
    const int m0   = blockIdx.x * 64;
    const unsigned full = 0xffffffffu;

    const int rl16 = lane & 15;
    const int ksel = lane >> 4;
    const int g    = lane >> 2;
    const int tig  = lane & 3;

    // ================= Phase A: QKV GEMM (BM=64, BN=192) =================
    {
        const int warp_m = wid & 1;
        const int warp_n = wid >> 1;

        auto load_stage = [&](int kt, int s) {
            const int k0 = kt << 6;
            const uint32_t sa = sbase + s * K234_STAGE;
            const uint32_t sb = sa + 8192;
#pragma unroll
            for (int i = 0; i < 2; ++i) {
                const int id = tid + 256 * i;
                const int row = id >> 3, c = id & 7;
                CP_ASYNC16(sa + row * 128 + ((c ^ (row & 7)) << 4),
                           g_hth + (size_t)(m0 + row) * NH + k0 + c * 8);
            }
#pragma unroll
            for (int i = 0; i < 6; ++i) {
                const int id = tid + 256 * i;
                const int row = id >> 3, c = id & 7;
                CP_ASYNC16(sb + row * 128 + ((c ^ (row & 7)) << 4),
                           g_wqkv16 + (size_t)row * NH + k0 + c * 8);
            }
        };

        float acc[2][6][4];
#pragma unroll
        for (int a = 0; a < 2; ++a)
#pragma unroll
            for (int b = 0; b < 6; ++b)
#pragma unroll
                for (int d = 0; d < 4; ++d) acc[a][b][d] = 0.f;

        load_stage(0, 0); CP_COMMIT();
        load_stage(1, 1); CP_COMMIT();

        uint32_t aOff[2]; int aSwz[2];
        uint32_t bOff[3]; int bSwz[3];
#pragma unroll
        for (int mt = 0; mt < 2; ++mt) {
            const int r = warp_m * 32 + mt * 16 + rl16;
            aOff[mt] = r * 128; aSwz[mt] = r & 7;
        }
#pragma unroll
        for (int p = 0; p < 3; ++p) {
            const int r = warp_n * 48 + p * 16 + rl16;
            bOff[p] = 8192 + r * 128; bSwz[p] = r & 7;
        }

        for (int kt = 0; kt < 32; ++kt) {
            const int s = kt % 3;
            CP_WAIT1();
            __syncthreads();
            if (kt + 2 < 32) load_stage(kt + 2, (kt + 2) % 3);
            CP_COMMIT();

            const uint32_t stage = sbase + s * K234_STAGE;
#pragma unroll
            for (int ks = 0; ks < 4; ++ks) {
                const int chunk = ks * 2 + ksel;
                uint32_t a[2][4], b[3][4];
#pragma unroll
                for (int mt = 0; mt < 2; ++mt)
                    LDMATRIX_X4(a[mt], stage + aOff[mt] + ((chunk ^ aSwz[mt]) << 4));
#pragma unroll
                for (int p = 0; p < 3; ++p)
                    LDMATRIX_X4(b[p], stage + bOff[p] + ((chunk ^ bSwz[p]) << 4));
#pragma unroll
                for (int mt = 0; mt < 2; ++mt)
#pragma unroll
                    for (int nt = 0; nt < 6; ++nt)
                        mma_f16(acc[mt][nt], a[mt],
                                b[nt >> 1][nt & 1], b[nt >> 1][2 + (nt & 1)]);
            }
        }

        CP_WAIT0();
        __syncthreads();

#pragma unroll
        for (int nt = 0; nt < 6; ++nt) {
            const int n = warp_n * 48 + nt * 8 + tig * 2;
#pragma unroll
            for (int mt = 0; mt < 2; ++mt) {
                int m = warp_m * 32 + mt * 16 + g;
                smf[m * QSTR + n]     = acc[mt][nt][0];
                smf[m * QSTR + n + 1] = acc[mt][nt][1];
                m += 8;
                smf[m * QSTR + n]     = acc[mt][nt][2];
                smf[m * QSTR + n + 1] = acc[mt][nt][3];
            }
        }
    }
    __syncthreads();

    // ================= Phase B: softmax routing =================
    {
#pragma unroll 1
        for (int rr = 0; rr < 8; ++rr) {
            const int r = wid * 8 + rr;
            const float* qk = smf + r * QSTR;
            const float q0s = 0.125f * qk[lane];
            const float q1s = 0.125f * qk[lane + 32];
            const float k0 = qk[64 + lane],  k1 = qk[96 + lane];
            const float v0 = qk[128 + lane], v1 = qk[160 + lane];

            float se0 = 0.f, sd0 = 0.f, se1 = 0.f, sd1 = 0.f;
#pragma unroll 8
            for (int j = 0; j < 32; ++j) {
                const float kj = __shfl_sync(full, k0, j);
                const float vj = __shfl_sync(full, v0, j);
                const float e0 = __expf(q0s * kj);
                const float e1 = __expf(q1s * kj);
                se0 += e0; sd0 = fmaf(e0, vj, sd0);
                se1 += e1; sd1 = fmaf(e1, vj, sd1);
            }
#pragma unroll 8
            for (int j = 0; j < 32; ++j) {
                const float kj = __shfl_sync(full, k1, j);
                const float vj = __shfl_sync(full, v1, j);
                const float e0 = __expf(q0s * kj);
                const float e1 = __expf(q1s * kj);
                se0 += e0; sd0 = fmaf(e0, vj, sd0);
                se1 += e1; sd1 = fmaf(e1, vj, sd1);
            }

            const int c0 = lane, c1 = lane + 32;
            sts_u16(sbase + RV_OFF + r * 128 +
                        (((c0 >> 3) ^ (r & 7)) << 4) + (c0 & 7) * 2,
                    __half_as_ushort(__float2half(sd0 / se0)));
            sts_u16(sbase + RV_OFF + r * 128 +
                        (((c1 >> 3) ^ (r & 7)) << 4) + (c1 & 7) * 2,
                    __half_as_ushort(__float2half(sd1 / se1)));
        }
    }
    __syncthreads();

    // ================= Phase C: y = gamma*(rv @ WO^T) + x_t =================
    {
        const int warp_m = wid & 1;
        const int warp_n = wid >> 1;
        const float gm = gamma[0];

        uint32_t fa[2][4][4];
#pragma unroll
        for (int mt = 0; mt < 2; ++mt) {
            const int r = warp_m * 32 + mt * 16 + rl16;
#pragma unroll
            for (int ks = 0; ks < 4; ++ks) {
                const int chunk = ks * 2 + ksel;
                LDMATRIX_X4(fa[mt][ks],
                            sbase + RV_OFF + r * 128 + ((chunk ^ (r & 7)) << 4));
            }
        }

        auto load_wo = [&](int t, int buf) {
            const uint32_t sb = sbase + WO_OFF + buf * 16384;
#pragma unroll
            for (int i = 0; i < 4; ++i) {
                const int id = tid + 256 * i;
                const int row = id >> 3, c = id & 7;
                CP_ASYNC16(sb + row * 128 + ((c ^ (row & 7)) << 4),
                           g_wo16 + (size_t)(t * 128 + row) * NR + c * 8);
            }
        };

        load_wo(0, 0); CP_COMMIT();

        for (int t = 0; t < 16; ++t) {
            if (t + 1 < 16) { load_wo(t + 1, (t + 1) & 1); CP_COMMIT(); CP_WAIT1(); }
            else            { CP_WAIT0(); }
            __syncthreads();

            const uint32_t sb = sbase + WO_OFF + (t & 1) * 16384;
            float acc[2][4][4];
#pragma unroll
            for (int a = 0; a < 2; ++a)
#pragma unroll
                for (int b = 0; b < 4; ++b)
#pragma unroll
                    for (int d = 0; d < 4; ++d) acc[a][b][d] = 0.f;

#pragma unroll
            for (int ks = 0; ks < 4; ++ks) {
                const int chunk = ks * 2 + ksel;
                uint32_t b[2][4];
#pragma unroll
                for (int p = 0; p < 2; ++p) {
                    const int r = warp_n * 32 + p * 16 + rl16;
                    LDMATRIX_X4(b[p], sb + r * 128 + ((chunk ^ (r & 7)) << 4));
                }
#pragma unroll
                for (int mt = 0; mt < 2; ++mt)
#pragma unroll
                    for (int nt = 0; nt < 4; ++nt)
                        mma_f16(acc[mt][nt], fa[mt][ks],
                                b[nt >> 1][nt & 1], b[nt >> 1][2 + (nt & 1)]);
            }

            const int nBase = t * 128 + warp_n * 32;
#pragma unroll
            for (int nt = 0; nt < 4; ++nt) {
                const int n = nBase + nt * 8 + tig * 2;
#pragma unroll
                for (int mt = 0; mt < 2; ++mt) {
                    int m = m0 + warp_m * 32 + mt * 16 + g;
                    float2 xv = *(const float2*)(x_t + (size_t)m * NH + n);
                    float2 o;
                    o.x = fmaf(gm, acc[mt][nt][0], xv.x);
                    o.y = fmaf(gm, acc[mt][nt][1], xv.y);
                    *(float2*)(y + (size_t)m * NH + n) = o;
                    m += 8;
                    xv = *(const float2*)(x_t + (size_t)m * NH + n);
                    o.x = fmaf(gm, acc[mt][nt][2], xv.x);
                    o.y = fmaf(gm, acc[mt][nt][3], xv.y);
                    *(float2*)(y + (size_t)m * NH + n) = o;
                }
            }
            __syncthreads();
        }
    }
}

// ---------------------------------------------------------------------------
extern "C" void kernel_launch(void* const* d_in, const int* in_sizes, int n_in,
                              void* d_out, int out_size)
{
    const float* h_prev    = (const float*)d_in[0];
    const float* x_t       = (const float*)d_in[1];
    const float* U_w       = (const float*)d_in[2];
    const float* U_b       = (const float*)d_in[3];
    const float* W_w       = (const float*)d_in[4];
    const float* alpha_raw = (const float*)d_in[5];
    const float* WQ        = (const float*)d_in[6];
    const float* WK        = (const float*)d_in[7];
    const float* WV        = (const float*)d_in[8];
    const float* WO        = (const float*)d_in[9];
    const float* gamma     = (const float*)d_in[10];

    float* h_t = (float*)d_out;
    float* y_t = h_t + (size_t)NB * NH;

    cudaFuncSetAttribute(k1_liquid_f16,
                         cudaFuncAttributeMaxDynamicSharedMemorySize, K1_SMEM);
    cudaFuncSetAttribute(k234_fused,
                         cudaFuncAttributeMaxDynamicSharedMemorySize, K234_SMEM);

    cvt_all<<<(CVT_TOTAL4 + 1023) / 1024, 256>>>(h_prev, x_t, W_w, U_w,
                                                 WQ, WK, WV, WO);

    dim3 g1(NH / 64, NB / 128);                       // (32, 64) = 2048 CTAs
    k1_liquid_f16<<<g1, 256, K1_SMEM>>>(h_prev, U_b, alpha_raw, h_t);

    k234_fused<<<NB / 64, 256, K234_SMEM>>>(x_t, gamma, y_t);
}

// round 11
// speedup vs baseline: 1.1666x; 1.0410x over previous
#include <cuda_runtime.h>
#include <cuda_fp16.h>
#include <math.h>
#include <stdint.h>

#define NB 8192
#define NH 2048
#define NR 64

// fp16 scratch
__device__ __half g_hp16[NB * NH];
__device__ __half g_xt16[NB * NH];
__device__ __half g_ww16[NH * NH];
__device__ __half g_uw16[NH * NH];
__device__ __half g_wqkv16[3 * NR * NH];   // rows 0-63 WQ | 64-127 WK | 128-191 WV
__device__ __half g_wo16[NH * NR];
__device__ __half g_hth[NB * NH];          // h_t fp16 (k1 -> k234)

// split-K scratch for k1's last 136 tiles
#define K1_FULL_TILES 888
#define K1_SPLIT_TILES 136                  // 1024 - 888
__device__ float g_part[K1_SPLIT_TILES * 16384];   // 8.9MB partials
__device__ int   g_flag[K1_SPLIT_TILES];

// ---------------------------------------------------------------------------
// helpers (sm_80-compatible; NO 'a'-suffix features)
// ---------------------------------------------------------------------------
__device__ __forceinline__ uint32_t smem_u32(const void* p) {
    uint32_t a;
    asm("{ .reg .u64 t; cvta.to.shared.u64 t, %1; cvt.u32.u64 %0, t; }"
        : "=r"(a) : "l"(p));
    return a;
}
#define LDMATRIX_X4(r, addr)                                                    \
    asm volatile("ldmatrix.sync.aligned.m8n8.x4.shared.b16 {%0,%1,%2,%3}, [%4];"\
        : "=r"((r)[0]), "=r"((r)[1]), "=r"((r)[2]), "=r"((r)[3]) : "r"(addr))

__device__ __forceinline__ void mma_f16(float c[4], const uint32_t a[4],
                                        uint32_t b0, uint32_t b1) {
    asm volatile(
        "mma.sync.aligned.m16n8k16.row.col.f32.f16.f16.f32 "
        "{%0,%1,%2,%3}, {%4,%5,%6,%7}, {%8,%9}, {%0,%1,%2,%3};"
        : "+f"(c[0]), "+f"(c[1]), "+f"(c[2]), "+f"(c[3])
        : "r"(a[0]), "r"(a[1]), "r"(a[2]), "r"(a[3]), "r"(b0), "r"(b1));
}

#define CP_ASYNC16(saddr, gptr)                                                \
    asm volatile("cp.async.cg.shared.global [%0], [%1], 16;"                   \
        :: "r"(saddr), "l"(gptr) : "memory")
#define CP_COMMIT() asm volatile("cp.async.commit_group;" ::: "memory")
#define CP_WAIT1()  asm volatile("cp.async.wait_group 1;" ::: "memory")
#define CP_WAIT0()  asm volatile("cp.async.wait_group 0;" ::: "memory")

__device__ __forceinline__ void sts_u16(uint32_t addr, uint16_t v) {
    asm volatile("st.shared.u16 [%0], %1;" :: "r"(addr), "h"(v));
}

// ---------------------------------------------------------------------------
// fused pre-pass: all fp32 -> fp16 (R8 version) + zero split-K flags
// ---------------------------------------------------------------------------
#define CVT_TOTAL4 10616832
__global__ __launch_bounds__(256)
void cvt_all(const float* __restrict__ hp, const float* __restrict__ xt,
             const float* __restrict__ ww, const float* __restrict__ uw,
             const float* __restrict__ wq, const float* __restrict__ wk,
             const float* __restrict__ wv, const float* __restrict__ wo)
{
    if (blockIdx.x == 0 && threadIdx.x < K1_SPLIT_TILES)
        g_flag[threadIdx.x] = 0;

    const int base = blockIdx.x * 1024 + threadIdx.x;
#pragma unroll
    for (int it = 0; it < 4; ++it) {
        const int i = base + it * 256;
        if (i >= CVT_TOTAL4) return;
        const float* src; __half* dst; int off;
        if (i < 4194304)        { src = hp; dst = g_hp16; off = i; }
        else if (i < 8388608)   { src = xt; dst = g_xt16; off = i - 4194304; }
        else if (i < 9437184)   { src = ww; dst = g_ww16; off = i - 8388608; }
        else if (i < 10485760)  { src = uw; dst = g_uw16; off = i - 9437184; }
        else if (i < 10518528)  { src = wq; dst = g_wqkv16;              off = i - 10485760; }
        else if (i < 10551296)  { src = wk; dst = g_wqkv16 + 64 * NH;    off = i - 10518528; }
        else if (i < 10584064)  { src = wv; dst = g_wqkv16 + 128 * NH;   off = i - 10551296; }
        else                    { src = wo; dst = g_wo16;                off = i - 10584064; }
        float4 v = ((const float4*)src)[off];
        ((__half2*)dst)[2 * off]     = __floats2half2_rn(v.x, v.y);
        ((__half2*)dst)[2 * off + 1] = __floats2half2_rn(v.z, v.w);
    }
}

// ---------------------------------------------------------------------------
// Kernel 1 (fp16 mma): h_t = (1-sigmoid(alpha))*h_prev
//                            + tanh(h_prev@W_w^T + x_t@U_w^T + U_b)
// BM=128, BN=128, BK=64, 256 thr (2x4 warps, warp tile 64x32), 3-stage
// cp.async, occ 2. Grid = 1160 1-D:
//   bid <  888 : full tile (kt 0..63)  -- 888 = 3 x 296 slots, 3 packed waves
//   bid <  1024: z0 half (kt 0..31, hp@W_w) -> partial + flag
//   bid <  1160: z1 half (kt 32..63, xt@U_w) -> spin, combine, epilogue
// Last-wave split kills the 13% wave-quantization tail.
// ---------------------------------------------------------------------------
#define K1_STAGE 32768
#define K1_SMEM (3 * K1_STAGE)

__global__ __launch_bounds__(256, 2)
void k1_liquid_f16(const float* __restrict__ h_prev,
                   const float* __restrict__ U_b,
                   const float* __restrict__ alpha_raw,
                   float* __restrict__ h_t)
{
    extern __shared__ char sm[];
    const uint32_t sbase = smem_u32(sm);

    const int tid  = threadIdx.x;
    const int wid  = tid >> 5;
    const int lane = tid & 31;
    const int warp_m = wid & 1;
    const int warp_n = wid >> 1;

    // ---- role decode ----
    const int bid = blockIdx.x;
    int tile, ktlo, kthi, mode, sidx = 0;
    if (bid < K1_FULL_TILES)      { tile = bid; ktlo = 0; kthi = 64; mode = 0; }
    else if (bid < 1024)          { sidx = bid - K1_FULL_TILES;
                                    tile = K1_FULL_TILES + sidx;
                                    ktlo = 0;  kthi = 32; mode = 1; }
    else                          { sidx = bid - 1024;
                                    tile = K1_FULL_TILES + sidx;
                                    ktlo = 32; kthi = 64; mode = 2; }
    const int m0 = (tile >> 4) * 128;   // batch tile
    const int n0 = (tile & 15) * 128;   // hidden tile

    auto load_stage = [&](int kt, int s) {
        const __half* Asrc = (kt < 32) ? g_hp16 : g_xt16;
        const __half* Bsrc = (kt < 32) ? g_ww16 : g_uw16;
        const int k0 = (kt & 31) << 6;
        const uint32_t sa = sbase + s * K1_STAGE;
        const uint32_t sb = sa + 16384;
#pragma unroll
        for (int i = 0; i < 4; ++i) {
            const int id = tid + 256 * i;
            const int row = id >> 3, c = id & 7;
            CP_ASYNC16(sa + row * 128 + ((c ^ (row & 7)) << 4),
                       Asrc + (size_t)(m0 + row) * NH + k0 + c * 8);
        }
#pragma unroll
        for (int i = 0; i < 4; ++i) {
            const int id = tid + 256 * i;
            const int row = id >> 3, c = id & 7;
            CP_ASYNC16(sb + row * 128 + ((c ^ (row & 7)) << 4),
                       Bsrc + (size_t)(n0 + row) * NH + k0 + c * 8);
        }
    };

    float acc[4][4][4];
#pragma unroll
    for (int a = 0; a < 4; ++a)
#pragma unroll
        for (int b = 0; b < 4; ++b)
#pragma unroll
            for (int d = 0; d < 4; ++d) acc[a][b][d] = 0.f;

    load_stage(ktlo, 0);     CP_COMMIT();
    load_stage(ktlo + 1, 1); CP_COMMIT();

    const int rl16 = lane & 15;
    const int ksel = lane >> 4;
    uint32_t aOff[4]; int aSwz[4];
    uint32_t bOff[2]; int bSwz[2];
#pragma unroll
    for (int mt = 0; mt < 4; ++mt) {
        const int r = warp_m * 64 + mt * 16 + rl16;
        aOff[mt] = r * 128; aSwz[mt] = r & 7;
    }
#pragma unroll
    for (int p = 0; p < 2; ++p) {
        const int r = warp_n * 32 + p * 16 + rl16;
        bOff[p] = 16384 + r * 128; bSwz[p] = r & 7;
    }

    const int nkt = kthi - ktlo;
    for (int it = 0; it < nkt; ++it) {
        const int s = it % 3;
        CP_WAIT1();
        __syncthreads();
        if (it + 2 < nkt) load_stage(ktlo + it + 2, (it + 2) % 3);
        CP_COMMIT();

        const uint32_t stage = sbase + s * K1_STAGE;
#pragma unroll
        for (int ks = 0; ks < 4; ++ks) {
            const int chunk = ks * 2 + ksel;
            uint32_t a[4][4], b[2][4];
#pragma unroll
            for (int mt = 0; mt < 4; ++mt)
                LDMATRIX_X4(a[mt], stage + aOff[mt] + ((chunk ^ aSwz[mt]) << 4));
#pragma unroll
            for (int p = 0; p < 2; ++p)
                LDMATRIX_X4(b[p], stage + bOff[p] + ((chunk ^ bSwz[p]) << 4));
#pragma unroll
            for (int mt = 0; mt < 4; ++mt)
#pragma unroll
                for (int nt = 0; nt < 4; ++nt)
                    mma_f16(acc[mt][nt], a[mt],
                            b[nt >> 1][nt & 1], b[nt >> 1][2 + (nt & 1)]);
        }
    }

    // ---- z0: publish partial, set flag, exit ----
    if (mode == 1) {
        float* pbase = g_part + (size_t)sidx * 16384;
#pragma unroll
        for (int a = 0; a < 4; ++a)
#pragma unroll
            for (int b = 0; b < 4; ++b) {
                float4 v = make_float4(acc[a][b][0], acc[a][b][1],
                                       acc[a][b][2], acc[a][b][3]);
                *(float4*)(pbase + (a * 4 + b) * 1024 + tid * 4) = v;
            }
        __threadfence();
        __syncthreads();
        if (tid == 0) atomicExch(&g_flag[sidx], 1);
        return;
    }

    // ---- z1: wait for z0, combine ----
    if (mode == 2) {
        if (tid == 0) {
            while (((volatile int*)g_flag)[sidx] == 0) __nanosleep(200);
        }
        __syncthreads();
        __threadfence();
        const float* pbase = g_part + (size_t)sidx * 16384;
#pragma unroll
        for (int a = 0; a < 4; ++a)
#pragma unroll
            for (int b = 0; b < 4; ++b) {
                float4 v = __ldcg((const float4*)(pbase + (a * 4 + b) * 1024 + tid * 4));
                acc[a][b][0] += v.x; acc[a][b][1] += v.y;
                acc[a][b][2] += v.z; acc[a][b][3] += v.w;
            }
    }

    // ---- epilogue (full tiles and z1) ----
    const int g = lane >> 2, tig = lane & 3;
    const int mBase = m0 + warp_m * 64;
    const int nBase = n0 + warp_n * 32;
#pragma unroll
    for (int nt = 0; nt < 4; ++nt) {
        const int n = nBase + nt * 8 + tig * 2;
        const float om0 = 1.f / (1.f + __expf(alpha_raw[n]));
        const float om1 = 1.f / (1.f + __expf(alpha_raw[n + 1]));
        const float bi0 = U_b[n], bi1 = U_b[n + 1];
#pragma unroll
        for (int mt = 0; mt < 4; ++mt) {
            int m = mBase + mt * 16 + g;
            float2 hp = *(const float2*)(h_prev + (size_t)m * NH + n);
            float2 o;
            o.x = om0 * hp.x + tanhf(acc[mt][nt][0] + bi0);
            o.y = om1 * hp.y + tanhf(acc[mt][nt][1] + bi1);
            *(float2*)(h_t + (size_t)m * NH + n) = o;
            *(__half2*)(g_hth + (size_t)m * NH + n) = __floats2half2_rn(o.x, o.y);
            m += 8;
            hp = *(const float2*)(h_prev + (size_t)m * NH + n);
            o.x = om0 * hp.x + tanhf(acc[mt][nt][2] + bi0);
            o.y = om1 * hp.y + tanhf(acc[mt][nt][3] + bi1);
            *(float2*)(h_t + (size_t)m * NH + n) = o;
            *(__half2*)(g_hth + (size_t)m * NH + n) = __floats2half2_rn(o.x, o.y);
        }
    }
}

// ---------------------------------------------------------------------------
// Kernel 234 (fused, unchanged from R8): per 64-row batch panel,
//   A) qkv = h_t @ [WQ;WK;WV]^T   B) routed softmax   C) y = gamma*rv@WO^T + x_t
// ---------------------------------------------------------------------------
#define K234_STAGE 32768
#define K234_SMEM  98304
#define QSTR 193
#define RV_OFF 53248
#define WO_OFF 61440

__global__ __launch_bounds__(256, 1)
void k234_fused(const float* __restrict__ x_t,
                const float* __restrict__ gamma,
                float* __restrict__ y)
{
    extern __shared__ char sm[];
    const uint32_t sbase = smem_u32(sm);
    float* smf = (float*)sm;

    const int tid  = threadIdx.x;
    const int wid  = tid >> 5;
    const int lane = tid & 31;
    const int m0   = blockIdx.x * 64;
    const unsigned full = 0xffffffffu;

    const int rl16 = lane & 15;
    const int ksel = lane >> 4;
    const int g    = lane >> 2;
    const int tig  = lane & 3;

    // ================= Phase A: QKV GEMM (BM=64, BN=192) =================
    {
        const int warp_m = wid & 1;
        const int warp_n = wid >> 1;

        auto load_stage = [&](int kt, int s) {
            const int k0 = kt << 6;
            const uint32_t sa = sbase + s * K234_STAGE;
            const uint32_t sb = sa + 8192;
#pragma unroll
            for (int i = 0; i < 2; ++i) {
                const int id = tid + 256 * i;
                const int row = id >> 3, c = id & 7;
                CP_ASYNC16(sa + row * 128 + ((c ^ (row & 7)) << 4),
                           g_hth + (size_t)(m0 + row) * NH + k0 + c * 8);
            }
#pragma unroll
            for (int i = 0; i < 6; ++i) {
                const int id = tid + 256 * i;
                const int row = id >> 3, c = id & 7;
                CP_ASYNC16(sb + row * 128 + ((c ^ (row & 7)) << 4),
                           g_wqkv16 + (size_t)row * NH + k0 + c * 8);
            }
        };

        float acc[2][6][4];
#pragma unroll
        for (int a = 0; a < 2; ++a)
#pragma unroll
            for (int b = 0; b < 6; ++b)
#pragma unroll
                for (int d = 0; d < 4; ++d) acc[a][b][d] = 0.f;

        load_stage(0, 0); CP_COMMIT();
        load_stage(1, 1); CP_COMMIT();

        uint32_t aOff[2]; int aSwz[2];
        uint32_t bOff[3]; int bSwz[3];
#pragma unroll
        for (int mt = 0; mt < 2; ++mt) {
            const int r = warp_m * 32 + mt * 16 + rl16;
            aOff[mt] = r * 128; aSwz[mt] = r & 7;
        }
#pragma unroll
        for (int p = 0; p < 3; ++p) {
            const int r = warp_n * 48 + p * 16 + rl16;
            bOff[p] = 8192 + r * 128; bSwz[p] = r & 7;
        }

        for (int kt = 0; kt < 32; ++kt) {
            const int s = kt % 3;
            CP_WAIT1();
            __syncthreads();
            if (kt + 2 < 32) load_stage(kt + 2, (kt + 2) % 3);
            CP_COMMIT();

            const uint32_t stage = sbase + s * K234_STAGE;
#pragma unroll
            for (int ks = 0; ks < 4; ++ks) {
                const int chunk = ks * 2 + ksel;
                uint32_t a[2][4], b[3][4];
#pragma unroll
                for (int mt = 0; mt < 2; ++mt)
                    LDMATRIX_X4(a[mt], stage + aOff[mt] + ((chunk ^ aSwz[mt]) << 4));
#pragma unroll
                for (int p = 0; p < 3; ++p)
                    LDMATRIX_X4(b[p], stage + bOff[p] + ((chunk ^ bSwz[p]) << 4));
#pragma unroll
                for (int mt = 0; mt < 2; ++mt)
#pragma unroll
                    for (int nt = 0; nt < 6; ++nt)
                        mma_f16(acc[mt][nt], a[mt],
                                b[nt >> 1][nt & 1], b[nt >> 1][2 + (nt & 1)]);
            }
        }

        CP_WAIT0();
        __syncthreads();

#pragma unroll
        for (int nt = 0; nt < 6; ++nt) {
            const int n = warp_n * 48 + nt * 8 + tig * 2;
#pragma unroll
            for (int mt = 0; mt < 2; ++mt) {
                int m = warp_m * 32 + mt * 16 + g;
                smf[m * QSTR + n]     = acc[mt][nt][0];
                smf[m * QSTR + n + 1] = acc[mt][nt][1];
                m += 8;
                smf[m * QSTR + n]     = acc[mt][nt][2];
                smf[m * QSTR + n + 1] = acc[mt][nt][3];
            }
        }
    }
    __syncthreads();

    // ================= Phase B: softmax routing =================
    {
#pragma unroll 1
        for (int rr = 0; rr < 8; ++rr) {
            const int r = wid * 8 + rr;
            const float* qk = smf + r * QSTR;
            const float q0s = 0.125f * qk[lane];
            const float q1s = 0.125f * qk[lane + 32];
            const float k0 = qk[64 + lane],  k1 = qk[96 + lane];
            const float v0 = qk[128 + lane], v1 = qk[160 + lane];

            float se0 = 0.f, sd0 = 0.f, se1 = 0.f, sd1 = 0.f;
#pragma unroll 8
            for (int j = 0; j < 32; ++j) {
                const float kj = __shfl_sync(full, k0, j);
                const float vj = __shfl_sync(full, v0, j);
                const float e0 = __expf(q0s * kj);
                const float e1 = __expf(q1s * kj);
                se0 += e0; sd0 = fmaf(e0, vj, sd0);
                se1 += e1; sd1 = fmaf(e1, vj, sd1);
            }
#pragma unroll 8
            for (int j = 0; j < 32; ++j) {
                const float kj = __shfl_sync(full, k1, j);
                const float vj = __shfl_sync(full, v1, j);
                const float e0 = __expf(q0s * kj);
                const float e1 = __expf(q1s * kj);
                se0 += e0; sd0 = fmaf(e0, vj, sd0);
                se1 += e1; sd1 = fmaf(e1, vj, sd1);
            }

            const int c0 = lane, c1 = lane + 32;
            sts_u16(sbase + RV_OFF + r * 128 +
                        (((c0 >> 3) ^ (r & 7)) << 4) + (c0 & 7) * 2,
                    __half_as_ushort(__float2half(sd0 / se0)));
            sts_u16(sbase + RV_OFF + r * 128 +
                        (((c1 >> 3) ^ (r & 7)) << 4) + (c1 & 7) * 2,
                    __half_as_ushort(__float2half(sd1 / se1)));
        }
    }
    __syncthreads();

    // ================= Phase C: y = gamma*(rv @ WO^T) + x_t =================
    {
        const int warp_m = wid & 1;
        const int warp_n = wid >> 1;
        const float gm = gamma[0];

        uint32_t fa[2][4][4];
#pragma unroll
        for (int mt = 0; mt < 2; ++mt) {
            const int r = warp_m * 32 + mt * 16 + rl16;
#pragma unroll
            for (int ks = 0; ks < 4; ++ks) {
                const int chunk = ks * 2 + ksel;
                LDMATRIX_X4(fa[mt][ks],
                            sbase + RV_OFF + r * 128 + ((chunk ^ (r & 7)) << 4));
            }
        }

        auto load_wo = [&](int t, int buf) {
            const uint32_t sb = sbase + WO_OFF + buf * 16384;
#pragma unroll
            for (int i = 0; i < 4; ++i) {
                const int id = tid + 256 * i;
                const int row = id >> 3, c = id & 7;
                CP_ASYNC16(sb + row * 128 + ((c ^ (row & 7)) << 4),
                           g_wo16 + (size_t)(t * 128 + row) * NR + c * 8);
            }
        };

        load_wo(0, 0); CP_COMMIT();

        for (int t = 0; t < 16; ++t) {
            if (t + 1 < 16) { load_wo(t + 1, (t + 1) & 1); CP_COMMIT(); CP_WAIT1(); }
            else            { CP_WAIT0(); }
            __syncthreads();

            const uint32_t sb = sbase + WO_OFF + (t & 1) * 16384;
            float acc[2][4][4];
#pragma unroll
            for (int a = 0; a < 2; ++a)
#pragma unroll
                for (int b = 0; b < 4; ++b)
#pragma unroll
                    for (int d = 0; d < 4; ++d) acc[a][b][d] = 0.f;

#pragma unroll
            for (int ks = 0; ks < 4; ++ks) {
                const int chunk = ks * 2 + ksel;
                uint32_t b[2][4];
#pragma unroll
                for (int p = 0; p < 2; ++p) {
                    const int r = warp_n * 32 + p * 16 + rl16;
                    LDMATRIX_X4(b[p], sb + r * 128 + ((chunk ^ (r & 7)) << 4));
                }
#pragma unroll
                for (int mt = 0; mt < 2; ++mt)
#pragma unroll
                    for (int nt = 0; nt < 4; ++nt)
                        mma_f16(acc[mt][nt], fa[mt][ks],
                                b[nt >> 1][nt & 1], b[nt >> 1][2 + (nt & 1)]);
            }

            const int nBase = t * 128 + warp_n * 32;
#pragma unroll
            for (int nt = 0; nt < 4; ++nt) {
                const int n = nBase + nt * 8 + tig * 2;
#pragma unroll
                for (int mt = 0; mt < 2; ++mt) {
                    int m = m0 + warp_m * 32 + mt * 16 + g;
                    float2 xv = *(const float2*)(x_t + (size_t)m * NH + n);
                    float2 o;
                    o.x = fmaf(gm, acc[mt][nt][0], xv.x);
                    o.y = fmaf(gm, acc[mt][nt][1], xv.y);
                    *(float2*)(y + (size_t)m * NH + n) = o;
                    m += 8;
                    xv = *(const float2*)(x_t + (size_t)m * NH + n);
                    o.x = fmaf(gm, acc[mt][nt][2], xv.x);
                    o.y = fmaf(gm, acc[mt][nt][3], xv.y);
                    *(float2*)(y + (size_t)m * NH + n) = o;
                }
            }
            __syncthreads();
        }
    }
}

// ---------------------------------------------------------------------------
extern "C" void kernel_launch(void* const* d_in, const int* in_sizes, int n_in,
                              void* d_out, int out_size)
{
    const float* h_prev    = (const float*)d_in[0];
    const float* x_t       = (const float*)d_in[1];
    const float* U_w       = (const float*)d_in[2];
    const float* U_b       = (const float*)d_in[3];
    const float* W_w       = (const float*)d_in[4];
    const float* alpha_raw = (const float*)d_in[5];
    const float* WQ        = (const float*)d_in[6];
    const float* WK        = (const float*)d_in[7];
    const float* WV        = (const float*)d_in[8];
    const float* WO        = (const float*)d_in[9];
    const float* gamma     = (const float*)d_in[10];

    float* h_t = (float*)d_out;
    float* y_t = h_t + (size_t)NB * NH;

    cudaFuncSetAttribute(k1_liquid_f16,
                         cudaFuncAttributeMaxDynamicSharedMemorySize, K1_SMEM);
    cudaFuncSetAttribute(k234_fused,
                         cudaFuncAttributeMaxDynamicSharedMemorySize, K234_SMEM);

    cvt_all<<<(CVT_TOTAL4 + 1023) / 1024, 256>>>(h_prev, x_t, W_w, U_w,
                                                 WQ, WK, WV, WO);

    k1_liquid_f16<<<1160, 256, K1_SMEM>>>(h_prev, U_b, alpha_raw, h_t);

    k234_fused<<<NB / 64, 256, K234_SMEM>>>(x_t, gamma, y_t);
}

// round 12
// speedup vs baseline: 1.2365x; 1.0600x over previous
#include <cuda_runtime.h>
#include <cuda_fp16.h>
#include <math.h>
#include <stdint.h>

#define NB 8192
#define NH 2048
#define NR 64

// fp16 scratch
__device__ __half g_hp16[NB * NH];
__device__ __half g_xt16[NB * NH];
__device__ __half g_ww16[NH * NH];
__device__ __half g_uw16[NH * NH];
__device__ __half g_wqkv16[3 * NR * NH];   // rows 0-63 WQ | 64-127 WK | 128-191 WV
__device__ __half g_wo16[NH * NR];
__device__ __half g_hth[NB * NH];          // h_t fp16 (k1 -> k234)

// conversion-completion counters: hp[0..64) xt[64..128) ww[128..144) uw[144..160)
__device__ int g_cnt[160];

// ---------------------------------------------------------------------------
// helpers (sm_80-compatible; NO 'a'-suffix features)
// ---------------------------------------------------------------------------
__device__ __forceinline__ uint32_t smem_u32(const void* p) {
    uint32_t a;
    asm("{ .reg .u64 t; cvta.to.shared.u64 t, %1; cvt.u32.u64 %0, t; }"
        : "=r"(a) : "l"(p));
    return a;
}
#define LDMATRIX_X4(r, addr)                                                    \
    asm volatile("ldmatrix.sync.aligned.m8n8.x4.shared.b16 {%0,%1,%2,%3}, [%4];"\
        : "=r"((r)[0]), "=r"((r)[1]), "=r"((r)[2]), "=r"((r)[3]) : "r"(addr))

__device__ __forceinline__ void mma_f16(float c[4], const uint32_t a[4],
                                        uint32_t b0, uint32_t b1) {
    asm volatile(
        "mma.sync.aligned.m16n8k16.row.col.f32.f16.f16.f32 "
        "{%0,%1,%2,%3}, {%4,%5,%6,%7}, {%8,%9}, {%0,%1,%2,%3};"
        : "+f"(c[0]), "+f"(c[1]), "+f"(c[2]), "+f"(c[3])
        : "r"(a[0]), "r"(a[1]), "r"(a[2]), "r"(a[3]), "r"(b0), "r"(b1));
}

#define CP_ASYNC16(saddr, gptr)                                                \
    asm volatile("cp.async.cg.shared.global [%0], [%1], 16;"                   \
        :: "r"(saddr), "l"(gptr) : "memory")
#define CP_COMMIT() asm volatile("cp.async.commit_group;" ::: "memory")
#define CP_WAIT1()  asm volatile("cp.async.wait_group 1;" ::: "memory")
#define CP_WAIT0()  asm volatile("cp.async.wait_group 0;" ::: "memory")

__device__ __forceinline__ void sts_u16(uint32_t addr, uint16_t v) {
    asm volatile("st.shared.u16 [%0], %1;" :: "r"(addr), "h"(v));
}

// ---------------------------------------------------------------------------
// Kernel 1 (fp16 mma + fused fp32->fp16 conversion):
//   h_t = (1-sigmoid(alpha))*h_prev + tanh(h_prev@W_w^T + x_t@U_w^T + U_b)
// GEMM: BM=128, BN=128, BK=64, 256 thr, 3-stage cp.async, occ 2 (R8 config,
// at the legacy-HMMA floor). NEW: each CTA converts a data slice before tile
// work; per-panel counters gate readers. Producer groups precede consumer
// groups in dispatch order, so spin ~ 0 and conversion hides under compute.
//   group g=blockIdx.y (16 CTAs): converts hp/xt panel g+1 (g0: panels 0,1)
//   groups 1..16 also convert ww/uw panel blockIdx.x, chunk by-1
//   groups 17..48: wqkv/wo (1 float4/thread, needed only by k234)
// ---------------------------------------------------------------------------
#define K1_STAGE 32768
#define K1_SMEM (3 * K1_STAGE)

__global__ __launch_bounds__(256, 2)
void k1_liquid_f16(const float* __restrict__ h_prev,
                   const float* __restrict__ x_t,
                   const float* __restrict__ W_w,
                   const float* __restrict__ U_w,
                   const float* __restrict__ WQ,
                   const float* __restrict__ WK,
                   const float* __restrict__ WV,
                   const float* __restrict__ WO,
                   const float* __restrict__ U_b,
                   const float* __restrict__ alpha_raw,
                   float* __restrict__ h_t)
{
    extern __shared__ char sm[];
    const uint32_t sbase = smem_u32(sm);

    const int tid  = threadIdx.x;
    const int wid  = tid >> 5;
    const int lane = tid & 31;
    const int warp_m = wid & 1;
    const int warp_n = wid >> 1;
    const int bx = blockIdx.x;        // hidden tile / ww panel id
    const int by = blockIdx.y;        // batch tile / group id
    const int m0 = by * 128;
    const int n0 = bx * 128;

    // ================= conversion phase =================
    auto cvt_chunk = [&](const float* __restrict__ src, __half* dst, int f4base) {
#pragma unroll 4
        for (int i = 0; i < 16; ++i) {
            const int idx = f4base + tid + 256 * i;
            float4 v = ((const float4*)src)[idx];
            ((__half2*)dst)[2 * idx]     = __floats2half2_rn(v.x, v.y);
            ((__half2*)dst)[2 * idx + 1] = __floats2half2_rn(v.z, v.w);
        }
    };

    if (by == 0) {
        cvt_chunk(h_prev, g_hp16, 0 * 65536 + bx * 4096);
        cvt_chunk(h_prev, g_hp16, 1 * 65536 + bx * 4096);
        cvt_chunk(x_t,   g_xt16, 0 * 65536 + bx * 4096);
        cvt_chunk(x_t,   g_xt16, 1 * 65536 + bx * 4096);
    } else if (by <= 62) {
        cvt_chunk(h_prev, g_hp16, (by + 1) * 65536 + bx * 4096);
        cvt_chunk(x_t,   g_xt16, (by + 1) * 65536 + bx * 4096);
    }
    if (by >= 1 && by <= 16) {
        cvt_chunk(W_w, g_ww16, bx * 65536 + (by - 1) * 4096);
        cvt_chunk(U_w, g_uw16, bx * 65536 + (by - 1) * 4096);
    }
    if (by >= 17) {   // wqkv + wo: 131072 float4 over groups 17..48
        const int gidx = ((by - 17) * 16 + bx) * 256 + tid;
        if (gidx < 131072) {
            const float* src; __half* dst; int off;
            if (gidx < 32768)      { src = WQ; dst = g_wqkv16;            off = gidx; }
            else if (gidx < 65536) { src = WK; dst = g_wqkv16 + 64 * NH;  off = gidx - 32768; }
            else if (gidx < 98304) { src = WV; dst = g_wqkv16 + 128 * NH; off = gidx - 65536; }
            else                   { src = WO; dst = g_wo16;              off = gidx - 98304; }
            float4 v = ((const float4*)src)[off];
            ((__half2*)dst)[2 * off]     = __floats2half2_rn(v.x, v.y);
            ((__half2*)dst)[2 * off + 1] = __floats2half2_rn(v.z, v.w);
        }
    }
    __syncthreads();
    if (tid == 0) {
        __threadfence();
        if (by == 0) {
            atomicAdd(&g_cnt[0], 1);  atomicAdd(&g_cnt[1], 1);
            atomicAdd(&g_cnt[64], 1); atomicAdd(&g_cnt[65], 1);
        } else if (by <= 62) {
            atomicAdd(&g_cnt[by + 1], 1);
            atomicAdd(&g_cnt[64 + by + 1], 1);
        }
        if (by >= 1 && by <= 16) {
            atomicAdd(&g_cnt[128 + bx], 1);
            atomicAdd(&g_cnt[144 + bx], 1);
        }
        volatile int* c = g_cnt;
        while (c[by] < 16 || c[64 + by] < 16 ||
               c[128 + bx] < 16 || c[144 + bx] < 16)
            __nanosleep(100);
    }
    __syncthreads();

    // ================= GEMM (R8 loop, unchanged) =================
    auto load_stage = [&](int kt, int s) {
        const __half* Asrc = (kt < 32) ? g_hp16 : g_xt16;
        const __half* Bsrc = (kt < 32) ? g_ww16 : g_uw16;
        const int k0 = (kt & 31) << 6;
        const uint32_t sa = sbase + s * K1_STAGE;
        const uint32_t sb = sa + 16384;
#pragma unroll
        for (int i = 0; i < 4; ++i) {
            const int id = tid + 256 * i;
            const int row = id >> 3, c = id & 7;
            CP_ASYNC16(sa + row * 128 + ((c ^ (row & 7)) << 4),
                       Asrc + (size_t)(m0 + row) * NH + k0 + c * 8);
        }
#pragma unroll
        for (int i = 0; i < 4; ++i) {
            const int id = tid + 256 * i;
            const int row = id >> 3, c = id & 7;
            CP_ASYNC16(sb + row * 128 + ((c ^ (row & 7)) << 4),
                       Bsrc + (size_t)(n0 + row) * NH + k0 + c * 8);
        }
    };

    float acc[4][4][4];
#pragma unroll
    for (int a = 0; a < 4; ++a)
#pragma unroll
        for (int b = 0; b < 4; ++b)
#pragma unroll
            for (int d = 0; d < 4; ++d) acc[a][b][d] = 0.f;

    load_stage(0, 0); CP_COMMIT();
    load_stage(1, 1); CP_COMMIT();

    const int rl16 = lane & 15;
    const int ksel = lane >> 4;
    uint32_t aOff[4]; int aSwz[4];
    uint32_t bOff[2]; int bSwz[2];
#pragma unroll
    for (int mt = 0; mt < 4; ++mt) {
        const int r = warp_m * 64 + mt * 16 + rl16;
        aOff[mt] = r * 128; aSwz[mt] = r & 7;
    }
#pragma unroll
    for (int p = 0; p < 2; ++p) {
        const int r = warp_n * 32 + p * 16 + rl16;
        bOff[p] = 16384 + r * 128; bSwz[p] = r & 7;
    }

    for (int kt = 0; kt < 64; ++kt) {
        const int s = kt % 3;
        CP_WAIT1();
        __syncthreads();
        if (kt + 2 < 64) load_stage(kt + 2, (kt + 2) % 3);
        CP_COMMIT();

        const uint32_t stage = sbase + s * K1_STAGE;
#pragma unroll
        for (int ks = 0; ks < 4; ++ks) {
            const int chunk = ks * 2 + ksel;
            uint32_t a[4][4], b[2][4];
#pragma unroll
            for (int mt = 0; mt < 4; ++mt)
                LDMATRIX_X4(a[mt], stage + aOff[mt] + ((chunk ^ aSwz[mt]) << 4));
#pragma unroll
            for (int p = 0; p < 2; ++p)
                LDMATRIX_X4(b[p], stage + bOff[p] + ((chunk ^ bSwz[p]) << 4));
#pragma unroll
            for (int mt = 0; mt < 4; ++mt)
#pragma unroll
                for (int nt = 0; nt < 4; ++nt)
                    mma_f16(acc[mt][nt], a[mt],
                            b[nt >> 1][nt & 1], b[nt >> 1][2 + (nt & 1)]);
        }
    }

    const int g = lane >> 2, tig = lane & 3;
    const int mBase = m0 + warp_m * 64;
    const int nBase = n0 + warp_n * 32;
#pragma unroll
    for (int nt = 0; nt < 4; ++nt) {
        const int n = nBase + nt * 8 + tig * 2;
        const float om0 = 1.f / (1.f + __expf(alpha_raw[n]));
        const float om1 = 1.f / (1.f + __expf(alpha_raw[n + 1]));
        const float bi0 = U_b[n], bi1 = U_b[n + 1];
#pragma unroll
        for (int mt = 0; mt < 4; ++mt) {
            int m = mBase + mt * 16 + g;
            float2 hp = *(const float2*)(h_prev + (size_t)m * NH + n);
            float2 o;
            o.x = om0 * hp.x + tanhf(acc[mt][nt][0] + bi0);
            o.y = om1 * hp.y + tanhf(acc[mt][nt][1] + bi1);
            *(float2*)(h_t + (size_t)m * NH + n) = o;
            *(__half2*)(g_hth + (size_t)m * NH + n) = __floats2half2_rn(o.x, o.y);
            m += 8;
            hp = *(const float2*)(h_prev + (size_t)m * NH + n);
            o.x = om0 * hp.x + tanhf(acc[mt][nt][2] + bi0);
            o.y = om1 * hp.y + tanhf(acc[mt][nt][3] + bi1);
            *(float2*)(h_t + (size_t)m * NH + n) = o;
            *(__half2*)(g_hth + (size_t)m * NH + n) = __floats2half2_rn(o.x, o.y);
        }
    }
}

// ---------------------------------------------------------------------------
// Kernel 234 (fused, unchanged from R8): per 64-row batch panel,
//   A) qkv = h_t @ [WQ;WK;WV]^T   B) routed softmax   C) y = gamma*rv@WO^T + x_t
// ---------------------------------------------------------------------------
#define K234_STAGE 32768
#define K234_SMEM  98304
#define QSTR 193
#define RV_OFF 53248
#define WO_OFF 61440

__global__ __launch_bounds__(256, 1)
void k234_fused(const float* __restrict__ x_t,
                const float* __restrict__ gamma,
                float* __restrict__ y)
{
    extern __shared__ char sm[];
    const uint32_t sbase = smem_u32(sm);
    float* smf = (float*)sm;

    const int tid  = threadIdx.x;
    const int wid  = tid >> 5;
    const int lane = tid & 31;
    const int m0   = blockIdx.x * 64;
    const unsigned full = 0xffffffffu;

    const int rl16 = lane & 15;
    const int ksel = lane >> 4;
    const int g    = lane >> 2;
    const int tig  = lane & 3;

    // ================= Phase A: QKV GEMM (BM=64, BN=192) =================
    {
        const int warp_m = wid & 1;
        const int warp_n = wid >> 1;

        auto load_stage = [&](int kt, int s) {
            const int k0 = kt << 6;
            const uint32_t sa = sbase + s * K234_STAGE;
            const uint32_t sb = sa + 8192;
#pragma unroll
            for (int i = 0; i < 2; ++i) {
                const int id = tid + 256 * i;
                const int row = id >> 3, c = id & 7;
                CP_ASYNC16(sa + row * 128 + ((c ^ (row & 7)) << 4),
                           g_hth + (size_t)(m0 + row) * NH + k0 + c * 8);
            }
#pragma unroll
            for (int i = 0; i < 6; ++i) {
                const int id = tid + 256 * i;
                const int row = id >> 3, c = id & 7;
                CP_ASYNC16(sb + row * 128 + ((c ^ (row & 7)) << 4),
                           g_wqkv16 + (size_t)row * NH + k0 + c * 8);
            }
        };

        float acc[2][6][4];
#pragma unroll
        for (int a = 0; a < 2; ++a)
#pragma unroll
            for (int b = 0; b < 6; ++b)
#pragma unroll
                for (int d = 0; d < 4; ++d) acc[a][b][d] = 0.f;

        load_stage(0, 0); CP_COMMIT();
        load_stage(1, 1); CP_COMMIT();

        uint32_t aOff[2]; int aSwz[2];
        uint32_t bOff[3]; int bSwz[3];
#pragma unroll
        for (int mt = 0; mt < 2; ++mt) {
            const int r = warp_m * 32 + mt * 16 + rl16;
            aOff[mt] = r * 128; aSwz[mt] = r & 7;
        }
#pragma unroll
        for (int p = 0; p < 3; ++p) {
            const int r = warp_n * 48 + p * 16 + rl16;
            bOff[p] = 8192 + r * 128; bSwz[p] = r & 7;
        }

        for (int kt = 0; kt < 32; ++kt) {
            const int s = kt % 3;
            CP_WAIT1();
            __syncthreads();
            if (kt + 2 < 32) load_stage(kt + 2, (kt + 2) % 3);
            CP_COMMIT();

            const uint32_t stage = sbase + s * K234_STAGE;
#pragma unroll
            for (int ks = 0; ks < 4; ++ks) {
                const int chunk = ks * 2 + ksel;
                uint32_t a[2][4], b[3][4];
#pragma unroll
                for (int mt = 0; mt < 2; ++mt)
                    LDMATRIX_X4(a[mt], stage + aOff[mt] + ((chunk ^ aSwz[mt]) << 4));
#pragma unroll
                for (int p = 0; p < 3; ++p)
                    LDMATRIX_X4(b[p], stage + bOff[p] + ((chunk ^ bSwz[p]) << 4));
#pragma unroll
                for (int mt = 0; mt < 2; ++mt)
#pragma unroll
                    for (int nt = 0; nt < 6; ++nt)
                        mma_f16(acc[mt][nt], a[mt],
                                b[nt >> 1][nt & 1], b[nt >> 1][2 + (nt & 1)]);
            }
        }

        CP_WAIT0();
        __syncthreads();

#pragma unroll
        for (int nt = 0; nt < 6; ++nt) {
            const int n = warp_n * 48 + nt * 8 + tig * 2;
#pragma unroll
            for (int mt = 0; mt < 2; ++mt) {
                int m = warp_m * 32 + mt * 16 + g;
                smf[m * QSTR + n]     = acc[mt][nt][0];
                smf[m * QSTR + n + 1] = acc[mt][nt][1];
                m += 8;
                smf[m * QSTR + n]     = acc[mt][nt][2];
                smf[m * QSTR + n + 1] = acc[mt][nt][3];
            }
        }
    }
    __syncthreads();

    // ================= Phase B: softmax routing =================
    {
#pragma unroll 1
        for (int rr = 0; rr < 8; ++rr) {
            const int r = wid * 8 + rr;
            const float* qk = smf + r * QSTR;
            const float q0s = 0.125f * qk[lane];
            const float q1s = 0.125f * qk[lane + 32];
            const float k0 = qk[64 + lane],  k1 = qk[96 + lane];
            const float v0 = qk[128 + lane], v1 = qk[160 + lane];

            float se0 = 0.f, sd0 = 0.f, se1 = 0.f, sd1 = 0.f;
#pragma unroll 8
            for (int j = 0; j < 32; ++j) {
                const float kj = __shfl_sync(full, k0, j);
                const float vj = __shfl_sync(full, v0, j);
                const float e0 = __expf(q0s * kj);
                const float e1 = __expf(q1s * kj);
                se0 += e0; sd0 = fmaf(e0, vj, sd0);
                se1 += e1; sd1 = fmaf(e1, vj, sd1);
            }
#pragma unroll 8
            for (int j = 0; j < 32; ++j) {
                const float kj = __shfl_sync(full, k1, j);
                const float vj = __shfl_sync(full, v1, j);
                const float e0 = __expf(q0s * kj);
                const float e1 = __expf(q1s * kj);
                se0 += e0; sd0 = fmaf(e0, vj, sd0);
                se1 += e1; sd1 = fmaf(e1, vj, sd1);
            }

            const int c0 = lane, c1 = lane + 32;
            sts_u16(sbase + RV_OFF + r * 128 +
                        (((c0 >> 3) ^ (r & 7)) << 4) + (c0 & 7) * 2,
                    __half_as_ushort(__float2half(sd0 / se0)));
            sts_u16(sbase + RV_OFF + r * 128 +
                        (((c1 >> 3) ^ (r & 7)) << 4) + (c1 & 7) * 2,
                    __half_as_ushort(__float2half(sd1 / se1)));
        }
    }
    __syncthreads();

    // ================= Phase C: y = gamma*(rv @ WO^T) + x_t =================
    {
        const int warp_m = wid & 1;
        const int warp_n = wid >> 1;
        const float gm = gamma[0];

        uint32_t fa[2][4][4];
#pragma unroll
        for (int mt = 0; mt < 2; ++mt) {
            const int r = warp_m * 32 + mt * 16 + rl16;
#pragma unroll
            for (int ks = 0; ks < 4; ++ks) {
                const int chunk = ks * 2 + ksel;
                LDMATRIX_X4(fa[mt][ks],
                            sbase + RV_OFF + r * 128 + ((chunk ^ (r & 7)) << 4));
            }
        }

        auto load_wo = [&](int t, int buf) {
            const uint32_t sb = sbase + WO_OFF + buf * 16384;
#pragma unroll
            for (int i = 0; i < 4; ++i) {
                const int id = tid + 256 * i;
                const int row = id >> 3, c = id & 7;
                CP_ASYNC16(sb + row * 128 + ((c ^ (row & 7)) << 4),
                           g_wo16 + (size_t)(t * 128 + row) * NR + c * 8);
            }
        };

        load_wo(0, 0); CP_COMMIT();

        for (int t = 0; t < 16; ++t) {
            if (t + 1 < 16) { load_wo(t + 1, (t + 1) & 1); CP_COMMIT(); CP_WAIT1(); }
            else            { CP_WAIT0(); }
            __syncthreads();

            const uint32_t sb = sbase + WO_OFF + (t & 1) * 16384;
            float acc[2][4][4];
#pragma unroll
            for (int a = 0; a < 2; ++a)
#pragma unroll
                for (int b = 0; b < 4; ++b)
#pragma unroll
                    for (int d = 0; d < 4; ++d) acc[a][b][d] = 0.f;

#pragma unroll
            for (int ks = 0; ks < 4; ++ks) {
                const int chunk = ks * 2 + ksel;
                uint32_t b[2][4];
#pragma unroll
                for (int p = 0; p < 2; ++p) {
                    const int r = warp_n * 32 + p * 16 + rl16;
                    LDMATRIX_X4(b[p], sb + r * 128 + ((chunk ^ (r & 7)) << 4));
                }
#pragma unroll
                for (int mt = 0; mt < 2; ++mt)
#pragma unroll
                    for (int nt = 0; nt < 4; ++nt)
                        mma_f16(acc[mt][nt], fa[mt][ks],
                                b[nt >> 1][nt & 1], b[nt >> 1][2 + (nt & 1)]);
            }

            const int nBase = t * 128 + warp_n * 32;
#pragma unroll
            for (int nt = 0; nt < 4; ++nt) {
                const int n = nBase + nt * 8 + tig * 2;
#pragma unroll
                for (int mt = 0; mt < 2; ++mt) {
                    int m = m0 + warp_m * 32 + mt * 16 + g;
                    float2 xv = *(const float2*)(x_t + (size_t)m * NH + n);
                    float2 o;
                    o.x = fmaf(gm, acc[mt][nt][0], xv.x);
                    o.y = fmaf(gm, acc[mt][nt][1], xv.y);
                    *(float2*)(y + (size_t)m * NH + n) = o;
                    m += 8;
                    xv = *(const float2*)(x_t + (size_t)m * NH + n);
                    o.x = fmaf(gm, acc[mt][nt][2], xv.x);
                    o.y = fmaf(gm, acc[mt][nt][3], xv.y);
                    *(float2*)(y + (size_t)m * NH + n) = o;
                }
            }
            __syncthreads();
        }
    }
}

// ---------------------------------------------------------------------------
extern "C" void kernel_launch(void* const* d_in, const int* in_sizes, int n_in,
                              void* d_out, int out_size)
{
    const float* h_prev    = (const float*)d_in[0];
    const float* x_t       = (const float*)d_in[1];
    const float* U_w       = (const float*)d_in[2];
    const float* U_b       = (const float*)d_in[3];
    const float* W_w       = (const float*)d_in[4];
    const float* alpha_raw = (const float*)d_in[5];
    const float* WQ        = (const float*)d_in[6];
    const float* WK        = (const float*)d_in[7];
    const float* WV        = (const float*)d_in[8];
    const float* WO        = (const float*)d_in[9];
    const float* gamma     = (const float*)d_in[10];

    float* h_t = (float*)d_out;
    float* y_t = h_t + (size_t)NB * NH;

    cudaFuncSetAttribute(k1_liquid_f16,
                         cudaFuncAttributeMaxDynamicSharedMemorySize, K1_SMEM);
    cudaFuncSetAttribute(k234_fused,
                         cudaFuncAttributeMaxDynamicSharedMemorySize, K234_SMEM);

    // zero conversion counters (graph-capturable, deterministic per replay)
    void* cnt_addr = nullptr;
    cudaGetSymbolAddress(&cnt_addr, g_cnt);
    cudaMemsetAsync(cnt_addr, 0, 160 * sizeof(int));

    dim3 g1(NH / 128, NB / 128);                      // (16, 64) = 1024 CTAs
    k1_liquid_f16<<<g1, 256, K1_SMEM>>>(h_prev, x_t, W_w, U_w,
                                        WQ, WK, WV, WO,
                                        U_b, alpha_raw, h_t);

    k234_fused<<<NB / 64, 256, K234_SMEM>>>(x_t, gamma, y_t);
}